// round 17
// baseline (speedup 1.0000x reference)
#include <cuda_runtime.h>
#include <cuda_fp16.h>
#include <cstdint>

#define C_DIM   256
#define NCODES  256
#define HW_DIM  32768       // 128*256
#define BATCH   4
#define M_TILE  128
#define N_TILE  128         // pixels per CTA
#define KC      32          // K-chunk
#define NKB     8           // 256 / 32

// Projection matrix as fp16 in m16n8k16 *fragment order*:
// d_Mfh[ ((((kb*2 + h)*8 + r16)*2 + ks)*32 + lane)*8 + comp*2 + lo ]
//   kb = K-chunk (32), h = M-half (128), r16 = m16 block in half, ks = k16 step
//   lane = g*4 + tg;  comp = hm + 2*hk  (a0..a3);  lo = k parity within pair
__device__ __half d_Mfh[C_DIM * C_DIM];

// ---------------------------------------------------------------------------
// gemm smem layout (bytes): 3 A stages of 8192, then 2 B stages of 8704
// B stage: 32 k-rows x 128 px fp16, row pitch 272B (17x16B -> LDSM conflict-free)
// ---------------------------------------------------------------------------
#define A_STAGE    8192
#define B_OFF      (3 * A_STAGE)         // 24576
#define B_PITCH    272
#define B_STAGE    (32 * B_PITCH)        // 8704
#define SMEM_BYTES (B_OFF + 2 * B_STAGE) // 41984 -> 2 CTAs/SM easily

__device__ __forceinline__ void mma_f16(float c[4],
                                        uint32_t a0, uint32_t a1, uint32_t a2, uint32_t a3,
                                        uint32_t b0, uint32_t b1) {
    asm volatile(
        "mma.sync.aligned.m16n8k16.row.col.f32.f16.f16.f32 "
        "{%0,%1,%2,%3}, {%4,%5,%6,%7}, {%8,%9}, {%0,%1,%2,%3};"
        : "+f"(c[0]), "+f"(c[1]), "+f"(c[2]), "+f"(c[3])
        : "r"(a0), "r"(a1), "r"(a2), "r"(a3), "r"(b0), "r"(b1));
}
__device__ __forceinline__ void ldsm_x4_t(uint32_t& r0, uint32_t& r1,
                                          uint32_t& r2, uint32_t& r3, uint32_t addr) {
    asm volatile("ldmatrix.sync.aligned.m8n8.x4.trans.shared.b16 {%0,%1,%2,%3}, [%4];"
                 : "=r"(r0), "=r"(r1), "=r"(r2), "=r"(r3) : "r"(addr));
}
__device__ __forceinline__ void cp_async16(uint32_t smem_addr, const void* g) {
    asm volatile("cp.async.cg.shared.global [%0], [%1], 16;" :: "r"(smem_addr), "l"(g));
}
__device__ __forceinline__ void cp_commit() { asm volatile("cp.async.commit_group;"); }
__device__ __forceinline__ uint32_t h2pack(float x, float y) {
    __half2 h = __float22half2_rn(make_float2(x, y));
    return *(uint32_t*)&h;
}

// ---------------------------------------------------------------------------
// Kernel 0 (fused): inverse norms + M[i][j] = sum_n cb[n][i]*cb[n][j]/||cb_n||^2
// RN-rounded fp16, written in m16n8k16 fragment order.
// Grid (8,8): 32x32 output tile per block, 256 threads (16x16).
// Norms computed warp-per-row (coalesced float4), amortized over 32x32 tile.
// Dynamic smem: s_inv[256] + sI[256][32] + sJ[256][32] fp32.
// ---------------------------------------------------------------------------
__global__ void mmat_kernel(const float* __restrict__ cb) {
    extern __shared__ float dsm[];
    float* s_inv = dsm;                     // 256
    float* sI    = dsm + 256;               // [256][32]
    float* sJ    = sI + 256 * 32;           // [256][32]

    const int I0 = blockIdx.x * 32, J0 = blockIdx.y * 32;
    const int tid = threadIdx.x, lane = tid & 31, warp = tid >> 5;
    const int tx = tid & 15, ty = tid >> 4;

    // ---- norms: warp w handles rows w, w+8, ... (float4 coalesced) ----
    for (int r = warp; r < NCODES; r += 8) {
        const float4* row = (const float4*)(cb + r * C_DIM);
        float4 v0 = row[lane];
        float4 v1 = row[lane + 32];
        float s = v0.x * v0.x + v0.y * v0.y + v0.z * v0.z + v0.w * v0.w
                + v1.x * v1.x + v1.y * v1.y + v1.z * v1.z + v1.w * v1.w;
        #pragma unroll
        for (int off = 16; off; off >>= 1) s += __shfl_xor_sync(0xffffffffu, s, off);
        if (lane == 0) s_inv[r] = 1.0f / s;
    }
    __syncthreads();

    // ---- stage 32-wide column slices of cb ----
    for (int e = tid; e < NCODES * 32; e += 256) {
        int n = e >> 5, ii = e & 31;
        sI[n * 32 + ii] = cb[n * C_DIM + I0 + ii];
        sJ[n * 32 + ii] = cb[n * C_DIM + J0 + ii] * s_inv[n];
    }
    __syncthreads();

    // ---- 2x2 outputs per thread ----
    float a00 = 0, a01 = 0, a10 = 0, a11 = 0;
    #pragma unroll 4
    for (int n = 0; n < NCODES; n++) {
        float2 vi = *(const float2*)(sI + n * 32 + 2 * tx);
        float2 vj = *(const float2*)(sJ + n * 32 + 2 * ty);
        a00 += vi.x * vj.x; a01 += vi.x * vj.y;
        a10 += vi.y * vj.x; a11 += vi.y * vj.y;
    }

    // ---- fragment-order scatter (4 half stores) ----
    float av[4] = {a00, a01, a10, a11};
    #pragma unroll
    for (int q = 0; q < 4; q++) {
        int i = I0 + 2 * tx + (q >> 1);
        int j = J0 + 2 * ty + (q & 1);
        int h = i >> 7, r16 = (i >> 4) & 7, g = i & 7, hm = (i >> 3) & 1;
        int kb = j >> 5, ks = (j >> 4) & 1;
        int jj = j & 15, hk = jj >> 3, tg = (jj >> 1) & 3, lo = jj & 1;
        d_Mfh[(((((kb * 2 + h) * 8 + r16) * 2 + ks) * 32 + (g * 4 + tg)) * 8)
              + (hm + 2 * hk) * 2 + lo] = __float2half_rn(av[q]);
    }
}

// ---------------------------------------------------------------------------
// Kernel 1: out[b][c][p] = sum_k M[c][k] * feat[b][k][p]
// CTA 128(M) x 128(N), 256 threads (2 M-warps x 4 N-warps, 64x32 each).
// fp16 m16n8k16 MMAs; A via contiguous cp.async (fragment order, 3-stage);
// B: LDG.128 fp32 -> cvt.rn fp16 -> STS.64, consumed via ldmatrix.x4.trans
// (double-buffered). Grid (2 M-halves adjacent, HW/128, B); 2 CTAs/SM.
// ---------------------------------------------------------------------------
__global__ void __launch_bounds__(256, 2)
gemm_kernel(const float* __restrict__ feat, float* __restrict__ out) {
    extern __shared__ char smem[];
    const uint32_t sm_base = (uint32_t)__cvta_generic_to_shared(smem);

    const int tid  = threadIdx.x;
    const int lane = tid & 31;
    const int warp = tid >> 5;
    const int g    = lane >> 2;
    const int tg   = lane & 3;
    const int wm   = warp >> 2;          // 0..1, 64 M-rows each
    const int wn   = warp & 3;           // 0..3, 32 pixels each

    const int h  = blockIdx.x;           // M-half
    const int p0 = blockIdx.y * N_TILE;
    const int b  = blockIdx.z;
    const float* Bg = feat + (size_t)b * C_DIM * HW_DIM + p0;

    // A stage issue: 2 x 16B per thread (8KB stage, contiguous in gmem)
    auto issueA = [&](int kb, int s) {
        const char* src = (const char*)(d_Mfh + (size_t)(kb * 2 + h) * 4096);
        const uint32_t dst = sm_base + (uint32_t)(s * A_STAGE);
        cp_async16(dst + tid * 16, src + tid * 16);
        cp_async16(dst + 4096 + tid * 16, src + 4096 + tid * 16);
        cp_commit();
    };

    // B loader: 4 float4 per thread (rows tid>>5 + 8i, float4-col tid&31)
    const int b_row  = tid >> 5;
    const int b_col4 = tid & 31;

    // ldmatrix per-lane address component
    const uint32_t ldsm_lane = (uint32_t)(((lane & 7) + ((lane >> 3) & 1) * 8) * B_PITCH
                                          + (lane >> 4) * 16);

    float acc[4][4][4];
    #pragma unroll
    for (int mi = 0; mi < 4; mi++)
        #pragma unroll
        for (int ni = 0; ni < 4; ni++)
            #pragma unroll
            for (int q = 0; q < 4; q++) acc[mi][ni][q] = 0.0f;

    float4 rb[4];
    auto ldgB = [&](int kb) {
        #pragma unroll
        for (int i = 0; i < 4; i++)
            rb[i] = *(const float4*)(Bg + (size_t)(kb * KC + b_row + 8 * i) * HW_DIM
                                     + 4 * b_col4);
    };
    auto stsB = [&](int buf) {
        const uint32_t base = sm_base + B_OFF + buf * B_STAGE
                            + (uint32_t)(b_row * B_PITCH + b_col4 * 8);
        #pragma unroll
        for (int i = 0; i < 4; i++) {
            uint32_t lo = h2pack(rb[i].x, rb[i].y);
            uint32_t hi = h2pack(rb[i].z, rb[i].w);
            asm volatile("st.shared.v2.u32 [%0], {%1, %2};"
                         :: "r"(base + i * (8u * B_PITCH)), "r"(lo), "r"(hi));
        }
    };

    // ---- prologue ----
    issueA(0, 0);
    issueA(1, 1);
    ldgB(0);
    stsB(0);
    asm volatile("cp.async.wait_group 1;");
    __syncthreads();

    #pragma unroll 1
    for (int kb = 0; kb < NKB; kb++) {
        const int s   = kb % 3;
        const int buf = kb & 1;

        if (kb < NKB - 1) ldgB(kb + 1);
        if (kb + 2 < NKB) issueA(kb + 2, (kb + 2) % 3);

        const uint32_t Ast = sm_base + (uint32_t)(s * A_STAGE);
        const uint32_t Bst = sm_base + B_OFF + buf * B_STAGE;
        #pragma unroll
        for (int ks = 0; ks < 2; ks++) {
            uint4 a[4];
            #pragma unroll
            for (int mi = 0; mi < 4; mi++) {
                uint32_t addr = Ast + (uint32_t)((((wm * 4 + mi) * 2 + ks) * 32 + lane) * 16);
                asm volatile("ld.shared.v4.u32 {%0,%1,%2,%3}, [%4];"
                             : "=r"(a[mi].x), "=r"(a[mi].y), "=r"(a[mi].z), "=r"(a[mi].w)
                             : "r"(addr));
            }
            #pragma unroll
            for (int pair = 0; pair < 2; pair++) {
                uint32_t r0, r1, r2, r3;
                ldsm_x4_t(r0, r1, r2, r3,
                          Bst + (uint32_t)(ks * 16 * B_PITCH
                                           + (wn * 32 + pair * 16) * 2) + ldsm_lane);
                #pragma unroll
                for (int mi = 0; mi < 4; mi++) {
                    mma_f16(acc[mi][pair * 2 + 0], a[mi].x, a[mi].y, a[mi].z, a[mi].w, r0, r1);
                    mma_f16(acc[mi][pair * 2 + 1], a[mi].x, a[mi].y, a[mi].z, a[mi].w, r2, r3);
                }
            }
        }

        if (kb < NKB - 1) {
            stsB(buf ^ 1);
            if (kb == NKB - 2) asm volatile("cp.async.wait_group 0;");
            else               asm volatile("cp.async.wait_group 1;");
            __syncthreads();
        }
    }

    // ---- epilogue ----
    float* Og = out + (size_t)b * C_DIM * HW_DIM + (size_t)(h * M_TILE) * HW_DIM + p0;
    #pragma unroll
    for (int mi = 0; mi < 4; mi++) {
        int c0 = wm * 64 + mi * 16 + g;
        #pragma unroll
        for (int ni = 0; ni < 4; ni++) {
            int p = wn * 32 + ni * 8 + 2 * tg;
            *(float2*)(Og + (size_t)c0 * HW_DIM + p) =
                make_float2(acc[mi][ni][0], acc[mi][ni][1]);
            *(float2*)(Og + (size_t)(c0 + 8) * HW_DIM + p) =
                make_float2(acc[mi][ni][2], acc[mi][ni][3]);
        }
    }
}

// ---------------------------------------------------------------------------
extern "C" void kernel_launch(void* const* d_in, const int* in_sizes, int n_in,
                              void* d_out, int out_size) {
    const float* feat = (const float*)d_in[0];   // [B, C, H, W] fp32
    const float* cb   = (const float*)d_in[1];   // [N, C] fp32
    float* out        = (float*)d_out;           // [B, C, H, W] fp32

    const int mmat_smem = (256 + 2 * 256 * 32) * 4;   // 66560 B
    cudaFuncSetAttribute(mmat_kernel,
                         cudaFuncAttributeMaxDynamicSharedMemorySize, mmat_smem);
    mmat_kernel<<<dim3(8, 8), 256, mmat_smem>>>(cb);

    cudaFuncSetAttribute(gemm_kernel,
                         cudaFuncAttributeMaxDynamicSharedMemorySize, SMEM_BYTES);
    gemm_kernel<<<dim3(2, HW_DIM / N_TILE, BATCH), 256, SMEM_BYTES>>>(feat, out);
}